// round 8
// baseline (speedup 1.0000x reference)
#include <cuda_runtime.h>
#include <cuda_bf16.h>
#include <math.h>

// Problem constants
#define B_SZ   4
#define L_SEQ  2048
#define C_DIM  1024
#define H_NUM  16
#define DH     64
#define M_ROWS (B_SZ * L_SEQ)          // 8192
#define N_QKV  (3 * C_DIM)             // 3072
#define BH_NUM (B_SZ * H_NUM)          // 64

// ---------------------------------------------------------------------------
// Static device scratch
// ---------------------------------------------------------------------------
__device__ float g_qkv[M_ROWS * N_QKV];              // (B*L, 3C)
__device__ float g_q [BH_NUM * L_SEQ * DH];          // (bh,l,d-perm) tf32 bits, pre-scaled
__device__ float g_kT[BH_NUM * DH * L_SEQ];          // (bh,d,k-perm per 64-tile)
__device__ float g_vP[BH_NUM * L_SEQ * DH];          // (bh,k,d-perm)
__device__ float g_y[M_ROWS * C_DIM];                // (B*L, C)
__device__ float g_cs[L_SEQ][32];                    // RoPE cos table
__device__ float g_sn[L_SEQ][32];                    // RoPE sin table
__device__ float g_pb[M_ROWS];                       // pad bias (0 or -1e30)

// ---------------------------------------------------------------------------
// helpers
// ---------------------------------------------------------------------------
__device__ __forceinline__ unsigned f2tf(float f) {
    unsigned u;
    asm("cvt.rna.tf32.f32 %0, %1;" : "=r"(u) : "f"(f));
    return u;
}

__device__ __forceinline__ void mma_tf32(float* c, const unsigned* a, const unsigned* b) {
    asm("mma.sync.aligned.m16n8k8.row.col.f32.tf32.tf32.f32 "
        "{%0,%1,%2,%3}, {%4,%5,%6,%7}, {%8,%9}, {%0,%1,%2,%3};"
        : "+f"(c[0]), "+f"(c[1]), "+f"(c[2]), "+f"(c[3])
        : "r"(a[0]), "r"(a[1]), "r"(a[2]), "r"(a[3]), "r"(b[0]), "r"(b[1]));
}

__device__ __forceinline__ unsigned smaddr(const void* p) {
    return (unsigned)__cvta_generic_to_shared(p);
}

#define CP_ASYNC16(dst_u32, src) \
    asm volatile("cp.async.cg.shared.global [%0], [%1], 16;" :: "r"(dst_u32), "l"(src))
#define CP_ASYNC8(dst_u32, src) \
    asm volatile("cp.async.ca.shared.global [%0], [%1], 8;" :: "r"(dst_u32), "l"(src))
#define CP_COMMIT() asm volatile("cp.async.commit_group;")
#define CP_WAIT0()  asm volatile("cp.async.wait_group 0;" ::: "memory")

// ---------------------------------------------------------------------------
// tf32 GEMM + bias (unchanged from Round 6)
// ---------------------------------------------------------------------------
#define AS_STRIDE 20
#define BS_STRIDE 136

__device__ __forceinline__ void gemm_tc_body(const float* __restrict__ A,
                                             const float* __restrict__ Bm,
                                             const float* __restrict__ bias,
                                             float* __restrict__ C,
                                             int N, int K) {
    __shared__ float As[2][128 * AS_STRIDE];
    __shared__ float Bs[2][16 * BS_STRIDE];

    const int tid  = threadIdx.x;
    const int lane = tid & 31;
    const int wid  = tid >> 5;
    const int warp_m = wid & 1;
    const int warp_n = wid >> 1;
    const int grp = lane >> 2;
    const int tig = lane & 3;

    const int rowBlock = blockIdx.y * 128;
    const int colBlock = blockIdx.x * 128;
    const float* Abase = A + (size_t)rowBlock * K;

    float acc[4][4][4];
#pragma unroll
    for (int mt = 0; mt < 4; mt++)
#pragma unroll
        for (int nt = 0; nt < 4; nt++)
#pragma unroll
            for (int r = 0; r < 4; r++) acc[mt][nt][r] = 0.f;

    const int nk = K >> 4;

#pragma unroll
    for (int p = 0; p < 2; p++) {
        int c = p * 256 + tid;
        int row = c >> 2, k4 = (c & 3) * 4;
        CP_ASYNC16(smaddr(&As[0][row * AS_STRIDE + k4]),
                   Abase + (size_t)row * K + k4);
        int kr = c >> 5, n4 = (c & 31) * 4;
        CP_ASYNC16(smaddr(&Bs[0][kr * BS_STRIDE + n4]),
                   Bm + (size_t)kr * N + colBlock + n4);
    }
    CP_COMMIT();

    for (int kc = 0; kc < nk; kc++) {
        const int buf = kc & 1;
        CP_WAIT0();
        __syncthreads();

        if (kc + 1 < nk) {
            const int nb = buf ^ 1;
            const int kof = (kc + 1) * 16;
#pragma unroll
            for (int p = 0; p < 2; p++) {
                int c = p * 256 + tid;
                int row = c >> 2, k4 = (c & 3) * 4;
                CP_ASYNC16(smaddr(&As[nb][row * AS_STRIDE + k4]),
                           Abase + (size_t)row * K + kof + k4);
                int kr = c >> 5, n4 = (c & 31) * 4;
                CP_ASYNC16(smaddr(&Bs[nb][kr * BS_STRIDE + n4]),
                           Bm + (size_t)(kof + kr) * N + colBlock + n4);
            }
            CP_COMMIT();
        }

        const float* Ab = As[buf];
        const float* Bb = Bs[buf];
#pragma unroll
        for (int kk = 0; kk < 16; kk += 8) {
            unsigned af[4][4];
#pragma unroll
            for (int mt = 0; mt < 4; mt++) {
                int r0 = (warp_m * 64 + mt * 16 + grp) * AS_STRIDE + kk + tig;
                af[mt][0] = f2tf(Ab[r0]);
                af[mt][1] = f2tf(Ab[r0 + 8 * AS_STRIDE]);
                af[mt][2] = f2tf(Ab[r0 + 4]);
                af[mt][3] = f2tf(Ab[r0 + 8 * AS_STRIDE + 4]);
            }
            unsigned bf[4][2];
#pragma unroll
            for (int nt = 0; nt < 4; nt++) {
                int c0 = (kk + tig) * BS_STRIDE + warp_n * 32 + nt * 8 + grp;
                bf[nt][0] = f2tf(Bb[c0]);
                bf[nt][1] = f2tf(Bb[c0 + 4 * BS_STRIDE]);
            }
#pragma unroll
            for (int mt = 0; mt < 4; mt++)
#pragma unroll
                for (int nt = 0; nt < 4; nt++)
                    mma_tf32(acc[mt][nt], af[mt], bf[nt]);
        }
        __syncthreads();
    }

#pragma unroll
    for (int nt = 0; nt < 4; nt++) {
        int col = colBlock + warp_n * 32 + nt * 8 + tig * 2;
        float bx = bias[col], by = bias[col + 1];
#pragma unroll
        for (int mt = 0; mt < 4; mt++) {
            int row = rowBlock + warp_m * 64 + mt * 16 + grp;
            *reinterpret_cast<float2*>(C + (size_t)row * N + col) =
                make_float2(acc[mt][nt][0] + bx, acc[mt][nt][1] + by);
            *reinterpret_cast<float2*>(C + (size_t)(row + 8) * N + col) =
                make_float2(acc[mt][nt][2] + bx, acc[mt][nt][3] + by);
        }
    }
}

__global__ __launch_bounds__(256)
void qkv_gemm_kernel(const float* __restrict__ x,
                     const float* __restrict__ W,
                     const float* __restrict__ b) {
    gemm_tc_body(x, W, b, g_qkv, N_QKV, C_DIM);
}

__global__ __launch_bounds__(256)
void out_gemm_kernel(const float* __restrict__ W,
                     const float* __restrict__ b,
                     float* __restrict__ out) {
    gemm_tc_body(g_y, W, b, out, C_DIM, C_DIM);
}

// ---------------------------------------------------------------------------
// RoPE sin/cos table + pad bias
// ---------------------------------------------------------------------------
__global__ __launch_bounds__(256)
void rope_table_kernel(const unsigned char* __restrict__ pad) {
    int idx = blockIdx.x * 256 + threadIdx.x;
    if (idx < M_ROWS)
        g_pb[idx] = pad[idx] ? -1e30f : 0.f;
    if (idx >= L_SEQ * 32) return;
    int fi = idx & 31;
    int l  = idx >> 5;
    double invd = exp((double)fi * -0.28782313662425565);
    double ang  = (double)l * invd;
    g_cs[l][fi] = (float)cos(ang);
    g_sn[l][fi] = (float)sin(ang);
}

// ---------------------------------------------------------------------------
// RoPE + permuted layouts:
//  Q: (bh,l, (d%4)*16+d/4) tf32-bits, pre-scaled by 0.125*log2(e)
//  K: (bh,d, tile64: (k%8)*8+k/8)
//  V: (bh,k, (d%8)*8+d/8)
// ---------------------------------------------------------------------------
#define QK_SCALE 0.18033688011112042f   // 0.125 * log2(e)

__global__ __launch_bounds__(256)
void rope_transpose_kernel() {
    __shared__ float Tk[DH][65];

    const int tid = threadIdx.x;
    const int l0 = blockIdx.x * 64;
    const int bh = blockIdx.y;
    const int b  = bh >> 4;
    const int h  = bh & 15;

    float* qout = g_q  + (size_t)bh * L_SEQ * DH;
    float* vout = g_vP + (size_t)bh * L_SEQ * DH;

#pragma unroll
    for (int p = 0; p < 16; p++) {
        int e = p * 256 + tid;
        int l = e >> 6;
        int d = e & 63;
        int row  = b * L_SEQ + l0 + l;
        int base = row * N_QKV + h * DH;

        float qv = g_qkv[base + d];
        float kv = g_qkv[base + C_DIM + d];
        float vv = g_qkv[base + 2 * C_DIM + d];
        int d2 = (d < 32) ? d + 32 : d - 32;
        float qr = (d < 32) ? -g_qkv[base + d2] : g_qkv[base + d2];
        float kr = (d < 32) ? -g_qkv[base + C_DIM + d2] : g_qkv[base + C_DIM + d2];

        float cs = g_cs[l0 + l][d & 31];
        float sn = g_sn[l0 + l][d & 31];

        float qrot = fmaf(qv, cs, qr * sn) * QK_SCALE;
        qout[(l0 + l) * DH + (d & 3) * 16 + (d >> 2)] = __uint_as_float(f2tf(qrot));
        vout[(l0 + l) * DH + (d & 7) * 8 + (d >> 3)]  = vv;
        Tk[d][l] = fmaf(kv, cs, kr * sn);
    }
    __syncthreads();

    float* kout = g_kT + (size_t)bh * DH * L_SEQ;
#pragma unroll
    for (int p = 0; p < 16; p++) {
        int e = p * 256 + tid;
        int d = e >> 6;
        int l = e & 63;
        kout[d * L_SEQ + l0 + (l & 7) * 8 + (l >> 3)] = Tk[d][l];
    }
}

// ---------------------------------------------------------------------------
// Tensor-core flash attention: 128q x 64k, 128 threads (4 warps, mt=2).
// Permuted layouts -> vectorized conflict-free fragment LDS.64.
// SD=66 (rows 8B-aligned), cp.async.8 staging, double-buffered K/V.
// ---------------------------------------------------------------------------
#define SD 66
#define KV_WORDS (64 * SD)                         // 4224
#define Q_WORDS  (128 * SD)                        // 8448
#define FA_SMEM  ((Q_WORDS + 4 * KV_WORDS) * 4)    // 101376 bytes

__global__ __launch_bounds__(128)
void flash_attn_kernel() {
    extern __shared__ float sm[];
    float* Qs  = sm;
    float* Ks  = sm + Q_WORDS;
    float* Vsm = Ks + 2 * KV_WORDS;

    const int tid  = threadIdx.x;
    const int lane = tid & 31;
    const int wid  = tid >> 5;
    const int grp  = lane >> 2;
    const int tig  = lane & 3;

    const int qtb = (gridDim.x - 1) - blockIdx.x;  // big tiles first
    const int bh  = blockIdx.y;
    const int b   = bh >> 4;
    const int h   = bh & 15;
    const int q0  = qtb * 128;

    const float* qgbase = g_q  + ((size_t)bh * L_SEQ + q0) * DH;
    const float* kbase  = g_kT + (size_t)bh * DH * L_SEQ;
    const float* vbase  = g_vP + (size_t)bh * L_SEQ * DH;
    const float* pb     = g_pb + b * L_SEQ;

    // ---- stage Q (128x64) + first K/V tile (8B copies; permuted data) ----
#pragma unroll
    for (int p = 0; p < 32; p++) {
        int i = p * 128 + tid;
        int row = i >> 5, u = i & 31;
        CP_ASYNC8(smaddr(&Qs[row * SD + u * 2]), qgbase + (size_t)row * DH + u * 2);
    }
#pragma unroll
    for (int p = 0; p < 16; p++) {
        int i = p * 128 + tid;
        int row = i >> 5, u = i & 31;
        CP_ASYNC8(smaddr(&Ks[row * SD + u * 2]), kbase + (size_t)row * L_SEQ + u * 2);
        CP_ASYNC8(smaddr(&Vsm[row * SD + u * 2]), vbase + (size_t)row * DH + u * 2);
    }
    CP_COMMIT();

    float Oa[2][8][4];
#pragma unroll
    for (int mt = 0; mt < 2; mt++)
#pragma unroll
        for (int nt = 0; nt < 8; nt++)
#pragma unroll
            for (int r = 0; r < 4; r++) Oa[mt][nt][r] = 0.f;
    float mA[2] = {-INFINITY, -INFINITY};
    float mB[2] = {-INFINITY, -INFINITY};
    float lA[2] = {0.f, 0.f};
    float lB[2] = {0.f, 0.f};

    int rg0[2], rg1[2];
#pragma unroll
    for (int mt = 0; mt < 2; mt++) {
        rg0[mt] = q0 + wid * 32 + mt * 16 + grp;
        rg1[mt] = rg0[mt] + 8;
    }
    const int qrow_loc0 = wid * 32;

    const int psrc0 = (grp << 2) | (tig >> 1);
    const int psrc1 = psrc0 + 2;
    const bool podd = (tig & 1);

    const int nkt = 2 * qtb + 2;

    for (int kt = 0; kt < nkt; kt++) {
        const int k0  = kt * 64;
        const int buf = kt & 1;

        CP_WAIT0();
        __syncthreads();

        if (kt + 1 < nkt) {
            const int nb = buf ^ 1;
            const int nk0 = k0 + 64;
#pragma unroll
            for (int p = 0; p < 16; p++) {
                int i = p * 128 + tid;
                int row = i >> 5, u = i & 31;
                CP_ASYNC8(smaddr(&Ks[nb * KV_WORDS + row * SD + u * 2]),
                          kbase + (size_t)row * L_SEQ + nk0 + u * 2);
                CP_ASYNC8(smaddr(&Vsm[nb * KV_WORDS + row * SD + u * 2]),
                          vbase + (size_t)(nk0 + row) * DH + u * 2);
            }
            CP_COMMIT();
        }

        const float* Kb = Ks  + buf * KV_WORDS;
        const float* Vb = Vsm + buf * KV_WORDS;

        // ---- S = Q K^T (vectorized fragment loads) ----
        float sacc[2][8][4];
#pragma unroll
        for (int mt = 0; mt < 2; mt++)
#pragma unroll
            for (int nt = 0; nt < 8; nt++)
#pragma unroll
                for (int r = 0; r < 4; r++) sacc[mt][nt][r] = 0.f;

#pragma unroll
        for (int kc = 0; kc < 8; kc++) {
            const float2* kr0 = reinterpret_cast<const float2*>(&Kb[(kc * 8 + tig) * SD + grp * 8]);
            const float2* kr1 = reinterpret_cast<const float2*>(&Kb[(kc * 8 + tig + 4) * SD + grp * 8]);
            unsigned bf[8][2];
#pragma unroll
            for (int i = 0; i < 4; i++) {
                float2 a = kr0[i], c = kr1[i];
                bf[2 * i][0]     = __float_as_uint(a.x);
                bf[2 * i + 1][0] = __float_as_uint(a.y);
                bf[2 * i][1]     = __float_as_uint(c.x);
                bf[2 * i + 1][1] = __float_as_uint(c.y);
            }
#pragma unroll
            for (int mt = 0; mt < 2; mt++) {
                int rw = (qrow_loc0 + mt * 16 + grp) * SD + tig * 16 + 2 * kc;
                float2 q0v = *reinterpret_cast<const float2*>(&Qs[rw]);
                float2 q1v = *reinterpret_cast<const float2*>(&Qs[rw + 8 * SD]);
                unsigned af[4] = {__float_as_uint(q0v.x), __float_as_uint(q1v.x),
                                  __float_as_uint(q0v.y), __float_as_uint(q1v.y)};
#pragma unroll
                for (int nt = 0; nt < 8; nt++)
                    mma_tf32(sacc[mt][nt], af, bf[nt]);
            }
        }

        // ---- mask + online softmax (log2 domain) ----
        const bool diag = (kt >= 2 * qtb);
#pragma unroll
        for (int mt = 0; mt < 2; mt++) {
            float mx0 = -INFINITY, mx1 = -INFINITY;
#pragma unroll
            for (int nt = 0; nt < 8; nt++) {
                int c = nt * 8 + 2 * tig;
                float2 pbv = *reinterpret_cast<const float2*>(&pb[k0 + c]);
                float s0 = sacc[mt][nt][0] + pbv.x;
                float s1 = sacc[mt][nt][1] + pbv.y;
                float s2 = sacc[mt][nt][2] + pbv.x;
                float s3 = sacc[mt][nt][3] + pbv.y;
                if (diag) {
                    int col0 = k0 + c, col1 = col0 + 1;
                    if (col0 > rg0[mt]) s0 = -1e30f;
                    if (col1 > rg0[mt]) s1 = -1e30f;
                    if (col0 > rg1[mt]) s2 = -1e30f;
                    if (col1 > rg1[mt]) s3 = -1e30f;
                }
                sacc[mt][nt][0] = s0; sacc[mt][nt][1] = s1;
                sacc[mt][nt][2] = s2; sacc[mt][nt][3] = s3;
                mx0 = fmaxf(mx0, fmaxf(s0, s1));
                mx1 = fmaxf(mx1, fmaxf(s2, s3));
            }
            mx0 = fmaxf(mx0, __shfl_xor_sync(0xffffffffu, mx0, 1));
            mx0 = fmaxf(mx0, __shfl_xor_sync(0xffffffffu, mx0, 2));
            mx1 = fmaxf(mx1, __shfl_xor_sync(0xffffffffu, mx1, 1));
            mx1 = fmaxf(mx1, __shfl_xor_sync(0xffffffffu, mx1, 2));

            float mn0 = fmaxf(mA[mt], mx0);
            float mn1 = fmaxf(mB[mt], mx1);
            float corr0 = exp2f(mA[mt] - mn0);
            float corr1 = exp2f(mB[mt] - mn1);
            mA[mt] = mn0; mB[mt] = mn1;

            float rs0 = 0.f, rs1 = 0.f;
#pragma unroll
            for (int nt = 0; nt < 8; nt++) {
                float p0 = exp2f(sacc[mt][nt][0] - mn0);
                float p1 = exp2f(sacc[mt][nt][1] - mn0);
                float p2 = exp2f(sacc[mt][nt][2] - mn1);
                float p3 = exp2f(sacc[mt][nt][3] - mn1);
                sacc[mt][nt][0] = p0; sacc[mt][nt][1] = p1;
                sacc[mt][nt][2] = p2; sacc[mt][nt][3] = p3;
                rs0 += p0 + p1;
                rs1 += p2 + p3;
            }
            rs0 += __shfl_xor_sync(0xffffffffu, rs0, 1);
            rs0 += __shfl_xor_sync(0xffffffffu, rs0, 2);
            rs1 += __shfl_xor_sync(0xffffffffu, rs1, 1);
            rs1 += __shfl_xor_sync(0xffffffffu, rs1, 2);
            lA[mt] = lA[mt] * corr0 + rs0;
            lB[mt] = lB[mt] * corr1 + rs1;
#pragma unroll
            for (int nt = 0; nt < 8; nt++) {
                Oa[mt][nt][0] *= corr0; Oa[mt][nt][1] *= corr0;
                Oa[mt][nt][2] *= corr1; Oa[mt][nt][3] *= corr1;
            }
        }

        // ---- O += P V ----
#pragma unroll
        for (int kc = 0; kc < 8; kc++) {
            const float2* vr0 = reinterpret_cast<const float2*>(&Vb[(kc * 8 + tig) * SD + grp * 8]);
            const float2* vr1 = reinterpret_cast<const float2*>(&Vb[(kc * 8 + tig + 4) * SD + grp * 8]);
            unsigned bf[8][2];
#pragma unroll
            for (int i = 0; i < 4; i++) {
                float2 a = vr0[i], c = vr1[i];
                bf[2 * i][0]     = __float_as_uint(a.x);
                bf[2 * i + 1][0] = __float_as_uint(a.y);
                bf[2 * i][1]     = __float_as_uint(c.x);
                bf[2 * i + 1][1] = __float_as_uint(c.y);
            }
#pragma unroll
            for (int mt = 0; mt < 2; mt++) {
                float v0 = __shfl_sync(0xffffffffu, sacc[mt][kc][0], psrc0, 32);
                float v1 = __shfl_sync(0xffffffffu, sacc[mt][kc][1], psrc0, 32);
                float v2 = __shfl_sync(0xffffffffu, sacc[mt][kc][2], psrc0, 32);
                float v3 = __shfl_sync(0xffffffffu, sacc[mt][kc][3], psrc0, 32);
                float w0 = __shfl_sync(0xffffffffu, sacc[mt][kc][0], psrc1, 32);
                float w1 = __shfl_sync(0xffffffffu, sacc[mt][kc][1], psrc1, 32);
                float w2 = __shfl_sync(0xffffffffu, sacc[mt][kc][2], psrc1, 32);
                float w3 = __shfl_sync(0xffffffffu, sacc[mt][kc][3], psrc1, 32);
                unsigned af[4];
                af[0] = f2tf(podd ? v1 : v0);
                af[1] = f2tf(podd ? v3 : v2);
                af[2] = f2tf(podd ? w1 : w0);
                af[3] = f2tf(podd ? w3 : w2);
#pragma unroll
                for (int nt = 0; nt < 8; nt++)
                    mma_tf32(Oa[mt][nt], af, bf[nt]);
            }
        }
    }

    // ---- epilogue ----
#pragma unroll
    for (int mt = 0; mt < 2; mt++) {
        float inv0 = 1.f / lA[mt];
        float inv1 = 1.f / lB[mt];
        float* y0 = g_y + (size_t)(b * L_SEQ + rg0[mt]) * C_DIM + h * DH;
        float* y1 = g_y + (size_t)(b * L_SEQ + rg1[mt]) * C_DIM + h * DH;
#pragma unroll
        for (int nt = 0; nt < 8; nt++) {
            int c = nt * 8 + 2 * tig;
            *reinterpret_cast<float2*>(y0 + c) =
                make_float2(Oa[mt][nt][0] * inv0, Oa[mt][nt][1] * inv0);
            *reinterpret_cast<float2*>(y1 + c) =
                make_float2(Oa[mt][nt][2] * inv1, Oa[mt][nt][3] * inv1);
        }
    }
}

// ---------------------------------------------------------------------------
// Launch
// ---------------------------------------------------------------------------
extern "C" void kernel_launch(void* const* d_in, const int* in_sizes, int n_in,
                              void* d_out, int out_size) {
    const float*         x    = (const float*)d_in[0];
    const unsigned char* pad  = (const unsigned char*)d_in[1];
    const float*         Wqkv = (const float*)d_in[2];
    const float*         bqkv = (const float*)d_in[3];
    const float*         Wout = (const float*)d_in[4];
    const float*         bout = (const float*)d_in[5];
    float*               out  = (float*)d_out;

    cudaFuncSetAttribute(flash_attn_kernel,
                         cudaFuncAttributeMaxDynamicSharedMemorySize, FA_SMEM);

    rope_table_kernel<<<(L_SEQ * 32 + 255) / 256, 256>>>(pad);

    dim3 g1(N_QKV / 128, M_ROWS / 128);
    qkv_gemm_kernel<<<g1, 256>>>(x, Wqkv, bqkv);

    dim3 gr(L_SEQ / 64, BH_NUM);
    rope_transpose_kernel<<<gr, 256>>>();

    dim3 ga(L_SEQ / 128, BH_NUM);
    flash_attn_kernel<<<ga, 128, FA_SMEM>>>();

    dim3 g2(C_DIM / 128, M_ROWS / 128);
    out_gemm_kernel<<<g2, 256>>>(Wout, bout, out);
}

// round 10
// speedup vs baseline: 1.0782x; 1.0782x over previous
#include <cuda_runtime.h>
#include <cuda_bf16.h>
#include <math.h>

// Problem constants
#define B_SZ   4
#define L_SEQ  2048
#define C_DIM  1024
#define H_NUM  16
#define DH     64
#define M_ROWS (B_SZ * L_SEQ)          // 8192
#define N_QKV  (3 * C_DIM)             // 3072
#define BH_NUM (B_SZ * H_NUM)          // 64

// ---------------------------------------------------------------------------
// Static device scratch
// ---------------------------------------------------------------------------
__device__ float g_qkv[M_ROWS * N_QKV];              // (B*L, 3C)
__device__ float g_q [BH_NUM * L_SEQ * DH];          // (bh,l,d) tf32 BITS, pre-scaled
__device__ float g_kT[BH_NUM * DH * L_SEQ];          // (bh,d,L)
__device__ float g_y[M_ROWS * C_DIM];                // (B*L, C)
__device__ float g_cs[L_SEQ][32];                    // RoPE cos table
__device__ float g_sn[L_SEQ][32];                    // RoPE sin table
__device__ float g_pb[M_ROWS];                       // pad bias (0 or -1e30)

// ---------------------------------------------------------------------------
// helpers
// ---------------------------------------------------------------------------
__device__ __forceinline__ unsigned f2tf(float f) {
    unsigned u;
    asm("cvt.rna.tf32.f32 %0, %1;" : "=r"(u) : "f"(f));
    return u;
}

__device__ __forceinline__ void mma_tf32(float* c, const unsigned* a, const unsigned* b) {
    asm("mma.sync.aligned.m16n8k8.row.col.f32.tf32.tf32.f32 "
        "{%0,%1,%2,%3}, {%4,%5,%6,%7}, {%8,%9}, {%0,%1,%2,%3};"
        : "+f"(c[0]), "+f"(c[1]), "+f"(c[2]), "+f"(c[3])
        : "r"(a[0]), "r"(a[1]), "r"(a[2]), "r"(a[3]), "r"(b[0]), "r"(b[1]));
}

__device__ __forceinline__ unsigned smaddr(const void* p) {
    return (unsigned)__cvta_generic_to_shared(p);
}

#define CP_ASYNC16(dst_u32, src) \
    asm volatile("cp.async.cg.shared.global [%0], [%1], 16;" :: "r"(dst_u32), "l"(src))
#define CP_COMMIT() asm volatile("cp.async.commit_group;")
#define CP_WAIT0()  asm volatile("cp.async.wait_group 0;" ::: "memory")

// ---------------------------------------------------------------------------
// tf32 GEMM + bias (R6 version, unchanged)
// ---------------------------------------------------------------------------
#define AS_STRIDE 20
#define BS_STRIDE 136

__device__ __forceinline__ void gemm_tc_body(const float* __restrict__ A,
                                             const float* __restrict__ Bm,
                                             const float* __restrict__ bias,
                                             float* __restrict__ C,
                                             int N, int K) {
    __shared__ float As[2][128 * AS_STRIDE];
    __shared__ float Bs[2][16 * BS_STRIDE];

    const int tid  = threadIdx.x;
    const int lane = tid & 31;
    const int wid  = tid >> 5;
    const int warp_m = wid & 1;
    const int warp_n = wid >> 1;
    const int grp = lane >> 2;
    const int tig = lane & 3;

    const int rowBlock = blockIdx.y * 128;
    const int colBlock = blockIdx.x * 128;
    const float* Abase = A + (size_t)rowBlock * K;

    float acc[4][4][4];
#pragma unroll
    for (int mt = 0; mt < 4; mt++)
#pragma unroll
        for (int nt = 0; nt < 4; nt++)
#pragma unroll
            for (int r = 0; r < 4; r++) acc[mt][nt][r] = 0.f;

    const int nk = K >> 4;

#pragma unroll
    for (int p = 0; p < 2; p++) {
        int c = p * 256 + tid;
        int row = c >> 2, k4 = (c & 3) * 4;
        CP_ASYNC16(smaddr(&As[0][row * AS_STRIDE + k4]),
                   Abase + (size_t)row * K + k4);
        int kr = c >> 5, n4 = (c & 31) * 4;
        CP_ASYNC16(smaddr(&Bs[0][kr * BS_STRIDE + n4]),
                   Bm + (size_t)kr * N + colBlock + n4);
    }
    CP_COMMIT();

    for (int kc = 0; kc < nk; kc++) {
        const int buf = kc & 1;
        CP_WAIT0();
        __syncthreads();

        if (kc + 1 < nk) {
            const int nb = buf ^ 1;
            const int kof = (kc + 1) * 16;
#pragma unroll
            for (int p = 0; p < 2; p++) {
                int c = p * 256 + tid;
                int row = c >> 2, k4 = (c & 3) * 4;
                CP_ASYNC16(smaddr(&As[nb][row * AS_STRIDE + k4]),
                           Abase + (size_t)row * K + kof + k4);
                int kr = c >> 5, n4 = (c & 31) * 4;
                CP_ASYNC16(smaddr(&Bs[nb][kr * BS_STRIDE + n4]),
                           Bm + (size_t)(kof + kr) * N + colBlock + n4);
            }
            CP_COMMIT();
        }

        const float* Ab = As[buf];
        const float* Bb = Bs[buf];
#pragma unroll
        for (int kk = 0; kk < 16; kk += 8) {
            unsigned af[4][4];
#pragma unroll
            for (int mt = 0; mt < 4; mt++) {
                int r0 = (warp_m * 64 + mt * 16 + grp) * AS_STRIDE + kk + tig;
                af[mt][0] = f2tf(Ab[r0]);
                af[mt][1] = f2tf(Ab[r0 + 8 * AS_STRIDE]);
                af[mt][2] = f2tf(Ab[r0 + 4]);
                af[mt][3] = f2tf(Ab[r0 + 8 * AS_STRIDE + 4]);
            }
            unsigned bf[4][2];
#pragma unroll
            for (int nt = 0; nt < 4; nt++) {
                int c0 = (kk + tig) * BS_STRIDE + warp_n * 32 + nt * 8 + grp;
                bf[nt][0] = f2tf(Bb[c0]);
                bf[nt][1] = f2tf(Bb[c0 + 4 * BS_STRIDE]);
            }
#pragma unroll
            for (int mt = 0; mt < 4; mt++)
#pragma unroll
                for (int nt = 0; nt < 4; nt++)
                    mma_tf32(acc[mt][nt], af[mt], bf[nt]);
        }
        __syncthreads();
    }

#pragma unroll
    for (int nt = 0; nt < 4; nt++) {
        int col = colBlock + warp_n * 32 + nt * 8 + tig * 2;
        float bx = bias[col], by = bias[col + 1];
#pragma unroll
        for (int mt = 0; mt < 4; mt++) {
            int row = rowBlock + warp_m * 64 + mt * 16 + grp;
            *reinterpret_cast<float2*>(C + (size_t)row * N + col) =
                make_float2(acc[mt][nt][0] + bx, acc[mt][nt][1] + by);
            *reinterpret_cast<float2*>(C + (size_t)(row + 8) * N + col) =
                make_float2(acc[mt][nt][2] + bx, acc[mt][nt][3] + by);
        }
    }
}

__global__ __launch_bounds__(256)
void qkv_gemm_kernel(const float* __restrict__ x,
                     const float* __restrict__ W,
                     const float* __restrict__ b) {
    gemm_tc_body(x, W, b, g_qkv, N_QKV, C_DIM);
}

__global__ __launch_bounds__(256)
void out_gemm_kernel(const float* __restrict__ W,
                     const float* __restrict__ b,
                     float* __restrict__ out) {
    gemm_tc_body(g_y, W, b, out, C_DIM, C_DIM);
}

// ---------------------------------------------------------------------------
// RoPE sin/cos table + pad bias
// ---------------------------------------------------------------------------
__global__ __launch_bounds__(256)
void rope_table_kernel(const unsigned char* __restrict__ pad) {
    int idx = blockIdx.x * 256 + threadIdx.x;
    if (idx < M_ROWS)
        g_pb[idx] = pad[idx] ? -1e30f : 0.f;
    if (idx >= L_SEQ * 32) return;
    int fi = idx & 31;
    int l  = idx >> 5;
    double invd = exp((double)fi * -0.28782313662425565);
    double ang  = (double)l * invd;
    g_cs[l][fi] = (float)cos(ang);
    g_sn[l][fi] = (float)sin(ang);
}

// ---------------------------------------------------------------------------
// RoPE: Q -> g_q (bh,l,d) as tf32 BITS pre-scaled by 0.125*log2(e);
//       K -> g_kT (bh,d,L) transposed (plain layout).
// ---------------------------------------------------------------------------
#define QK_SCALE 0.18033688011112042f   // 0.125 * log2(e)

__global__ __launch_bounds__(256)
void rope_transpose_kernel() {
    __shared__ float Tk[DH][65];

    const int tid = threadIdx.x;
    const int l0 = blockIdx.x * 64;
    const int bh = blockIdx.y;
    const int b  = bh >> 4;
    const int h  = bh & 15;

    float* qout = g_q + (size_t)bh * L_SEQ * DH;

#pragma unroll
    for (int p = 0; p < 16; p++) {
        int e = p * 256 + tid;
        int l = e >> 6;
        int d = e & 63;
        int row  = b * L_SEQ + l0 + l;
        int base = row * N_QKV + h * DH;

        float qv = g_qkv[base + d];
        float kv = g_qkv[base + C_DIM + d];
        int d2 = (d < 32) ? d + 32 : d - 32;
        float qr = (d < 32) ? -g_qkv[base + d2] : g_qkv[base + d2];
        float kr = (d < 32) ? -g_qkv[base + C_DIM + d2] : g_qkv[base + C_DIM + d2];

        float cs = g_cs[l0 + l][d & 31];
        float sn = g_sn[l0 + l][d & 31];

        float qrot = fmaf(qv, cs, qr * sn) * QK_SCALE;
        qout[(l0 + l) * DH + d] = __uint_as_float(f2tf(qrot));   // tf32 bits
        Tk[d][l] = fmaf(kv, cs, kr * sn);
    }
    __syncthreads();

    float* kout = g_kT + (size_t)bh * DH * L_SEQ;
#pragma unroll
    for (int p = 0; p < 16; p++) {
        int e = p * 256 + tid;
        int d = e >> 6;
        int l = e & 63;
        kout[d * L_SEQ + l0 + l] = Tk[d][l];
    }
}

// ---------------------------------------------------------------------------
// Tensor-core flash attention (R6 structure): 128q x 64k, 128 threads,
// mt=2, Q in SMEM (tf32 bits, no cvt), K/V cp.async.16 double-buffered,
// exp2-domain softmax.
// ---------------------------------------------------------------------------
#define SD 68
#define KV_WORDS (64 * SD)                         // 4352 per buffer
#define Q_WORDS  (128 * SD)                        // 8704
#define FA_SMEM  ((Q_WORDS + 4 * KV_WORDS) * 4)    // 104448 bytes

__global__ __launch_bounds__(128)
void flash_attn_kernel() {
    extern __shared__ float sm[];
    float* Qs  = sm;                               // [128][SD] tf32 bits
    float* Ks  = sm + Q_WORDS;                     // [2][64*SD]
    float* Vsm = Ks + 2 * KV_WORDS;                // [2][64*SD]

    const int tid  = threadIdx.x;
    const int lane = tid & 31;
    const int wid  = tid >> 5;
    const int grp  = lane >> 2;
    const int tig  = lane & 3;

    const int qtb = (gridDim.x - 1) - blockIdx.x;  // big tiles first
    const int bh  = blockIdx.y;
    const int b   = bh >> 4;
    const int h   = bh & 15;
    const int q0  = qtb * 128;

    const float* qgbase = g_q  + ((size_t)bh * L_SEQ + q0) * DH;
    const float* kbase  = g_kT + (size_t)bh * DH * L_SEQ;
    const float* vgbase = g_qkv + (size_t)b * L_SEQ * N_QKV + 2 * C_DIM + h * DH;
    const float* pb     = g_pb + b * L_SEQ;

    // ---- stage Q (128x64) + first K/V tile ----
#pragma unroll
    for (int p = 0; p < 16; p++) {
        int c = p * 128 + tid;
        int row = c >> 4, c4 = (c & 15) * 4;
        CP_ASYNC16(smaddr(&Qs[row * SD + c4]), qgbase + (size_t)row * DH + c4);
    }
#pragma unroll
    for (int p = 0; p < 8; p++) {
        int i = p * 128 + tid;
        int row = i >> 4, c4 = (i & 15) * 4;
        CP_ASYNC16(smaddr(&Ks[row * SD + c4]), kbase + (size_t)row * L_SEQ + c4);
        CP_ASYNC16(smaddr(&Vsm[row * SD + c4]), vgbase + (size_t)row * N_QKV + c4);
    }
    CP_COMMIT();

    float Oa[2][8][4];
#pragma unroll
    for (int mt = 0; mt < 2; mt++)
#pragma unroll
        for (int nt = 0; nt < 8; nt++)
#pragma unroll
            for (int r = 0; r < 4; r++) Oa[mt][nt][r] = 0.f;
    float mA[2] = {-INFINITY, -INFINITY};
    float mB[2] = {-INFINITY, -INFINITY};
    float lA[2] = {0.f, 0.f};
    float lB[2] = {0.f, 0.f};

    int rg0[2], rg1[2];
#pragma unroll
    for (int mt = 0; mt < 2; mt++) {
        rg0[mt] = q0 + wid * 32 + mt * 16 + grp;
        rg1[mt] = rg0[mt] + 8;
    }
    const int qrow_loc0 = wid * 32;

    const int psrc0 = (grp << 2) | (tig >> 1);
    const int psrc1 = psrc0 + 2;
    const bool podd = (tig & 1);

    const int nkt = 2 * qtb + 2;

    for (int kt = 0; kt < nkt; kt++) {
        const int k0  = kt * 64;
        const int buf = kt & 1;

        CP_WAIT0();
        __syncthreads();

        if (kt + 1 < nkt) {
            const int nb = buf ^ 1;
            const int nk0 = k0 + 64;
#pragma unroll
            for (int p = 0; p < 8; p++) {
                int i = p * 128 + tid;
                int row = i >> 4, c4 = (i & 15) * 4;
                CP_ASYNC16(smaddr(&Ks[nb * KV_WORDS + row * SD + c4]),
                           kbase + (size_t)row * L_SEQ + nk0 + c4);
                CP_ASYNC16(smaddr(&Vsm[nb * KV_WORDS + row * SD + c4]),
                           vgbase + (size_t)(nk0 + row) * N_QKV + c4);
            }
            CP_COMMIT();
        }

        const float* Kb = Ks  + buf * KV_WORDS;
        const float* Vb = Vsm + buf * KV_WORDS;

        // ---- S = Q K^T ----
        float sacc[2][8][4];
#pragma unroll
        for (int mt = 0; mt < 2; mt++)
#pragma unroll
            for (int nt = 0; nt < 8; nt++)
#pragma unroll
                for (int r = 0; r < 4; r++) sacc[mt][nt][r] = 0.f;

#pragma unroll
        for (int kc = 0; kc < 8; kc++) {
            unsigned bf[8][2];
#pragma unroll
            for (int nt = 0; nt < 8; nt++) {
                int c0 = (kc * 8 + tig) * SD + nt * 8 + grp;
                bf[nt][0] = __float_as_uint(Kb[c0]);
                bf[nt][1] = __float_as_uint(Kb[c0 + 4 * SD]);
            }
#pragma unroll
            for (int mt = 0; mt < 2; mt++) {
                int r0 = (qrow_loc0 + mt * 16 + grp) * SD + kc * 8 + tig;
                unsigned af[4];
                af[0] = __float_as_uint(Qs[r0]);                 // pre-cvt'd
                af[1] = __float_as_uint(Qs[r0 + 8 * SD]);
                af[2] = __float_as_uint(Qs[r0 + 4]);
                af[3] = __float_as_uint(Qs[r0 + 8 * SD + 4]);
#pragma unroll
                for (int nt = 0; nt < 8; nt++)
                    mma_tf32(sacc[mt][nt], af, bf[nt]);
            }
        }

        // ---- mask + online softmax (log2 domain) ----
        const bool diag = (kt >= 2 * qtb);
#pragma unroll
        for (int mt = 0; mt < 2; mt++) {
            float mx0 = -INFINITY, mx1 = -INFINITY;
#pragma unroll
            for (int nt = 0; nt < 8; nt++) {
                int c = nt * 8 + 2 * tig;
                float2 pbv = *reinterpret_cast<const float2*>(&pb[k0 + c]);
                float s0 = sacc[mt][nt][0] + pbv.x;
                float s1 = sacc[mt][nt][1] + pbv.y;
                float s2 = sacc[mt][nt][2] + pbv.x;
                float s3 = sacc[mt][nt][3] + pbv.y;
                if (diag) {
                    int col0 = k0 + c, col1 = col0 + 1;
                    if (col0 > rg0[mt]) s0 = -1e30f;
                    if (col1 > rg0[mt]) s1 = -1e30f;
                    if (col0 > rg1[mt]) s2 = -1e30f;
                    if (col1 > rg1[mt]) s3 = -1e30f;
                }
                sacc[mt][nt][0] = s0; sacc[mt][nt][1] = s1;
                sacc[mt][nt][2] = s2; sacc[mt][nt][3] = s3;
                mx0 = fmaxf(mx0, fmaxf(s0, s1));
                mx1 = fmaxf(mx1, fmaxf(s2, s3));
            }
            mx0 = fmaxf(mx0, __shfl_xor_sync(0xffffffffu, mx0, 1));
            mx0 = fmaxf(mx0, __shfl_xor_sync(0xffffffffu, mx0, 2));
            mx1 = fmaxf(mx1, __shfl_xor_sync(0xffffffffu, mx1, 1));
            mx1 = fmaxf(mx1, __shfl_xor_sync(0xffffffffu, mx1, 2));

            float mn0 = fmaxf(mA[mt], mx0);
            float mn1 = fmaxf(mB[mt], mx1);
            float corr0 = exp2f(mA[mt] - mn0);
            float corr1 = exp2f(mB[mt] - mn1);
            mA[mt] = mn0; mB[mt] = mn1;

            float rs0 = 0.f, rs1 = 0.f;
#pragma unroll
            for (int nt = 0; nt < 8; nt++) {
                float p0 = exp2f(sacc[mt][nt][0] - mn0);
                float p1 = exp2f(sacc[mt][nt][1] - mn0);
                float p2 = exp2f(sacc[mt][nt][2] - mn1);
                float p3 = exp2f(sacc[mt][nt][3] - mn1);
                sacc[mt][nt][0] = p0; sacc[mt][nt][1] = p1;
                sacc[mt][nt][2] = p2; sacc[mt][nt][3] = p3;
                rs0 += p0 + p1;
                rs1 += p2 + p3;
            }
            rs0 += __shfl_xor_sync(0xffffffffu, rs0, 1);
            rs0 += __shfl_xor_sync(0xffffffffu, rs0, 2);
            rs1 += __shfl_xor_sync(0xffffffffu, rs1, 1);
            rs1 += __shfl_xor_sync(0xffffffffu, rs1, 2);
            lA[mt] = lA[mt] * corr0 + rs0;
            lB[mt] = lB[mt] * corr1 + rs1;
#pragma unroll
            for (int nt = 0; nt < 8; nt++) {
                Oa[mt][nt][0] *= corr0; Oa[mt][nt][1] *= corr0;
                Oa[mt][nt][2] *= corr1; Oa[mt][nt][3] *= corr1;
            }
        }

        // ---- O += P V ----
#pragma unroll
        for (int kc = 0; kc < 8; kc++) {
            unsigned bf[8][2];
#pragma unroll
            for (int nt = 0; nt < 8; nt++) {
                int c0 = (kc * 8 + tig) * SD + nt * 8 + grp;
                bf[nt][0] = __float_as_uint(Vb[c0]);
                bf[nt][1] = __float_as_uint(Vb[c0 + 4 * SD]);
            }
#pragma unroll
            for (int mt = 0; mt < 2; mt++) {
                float v0 = __shfl_sync(0xffffffffu, sacc[mt][kc][0], psrc0, 32);
                float v1 = __shfl_sync(0xffffffffu, sacc[mt][kc][1], psrc0, 32);
                float v2 = __shfl_sync(0xffffffffu, sacc[mt][kc][2], psrc0, 32);
                float v3 = __shfl_sync(0xffffffffu, sacc[mt][kc][3], psrc0, 32);
                float w0 = __shfl_sync(0xffffffffu, sacc[mt][kc][0], psrc1, 32);
                float w1 = __shfl_sync(0xffffffffu, sacc[mt][kc][1], psrc1, 32);
                float w2 = __shfl_sync(0xffffffffu, sacc[mt][kc][2], psrc1, 32);
                float w3 = __shfl_sync(0xffffffffu, sacc[mt][kc][3], psrc1, 32);
                unsigned af[4];
                af[0] = f2tf(podd ? v1 : v0);
                af[1] = f2tf(podd ? v3 : v2);
                af[2] = f2tf(podd ? w1 : w0);
                af[3] = f2tf(podd ? w3 : w2);
#pragma unroll
                for (int nt = 0; nt < 8; nt++)
                    mma_tf32(Oa[mt][nt], af, bf[nt]);
            }
        }
    }

    // ---- epilogue ----
#pragma unroll
    for (int mt = 0; mt < 2; mt++) {
        float inv0 = 1.f / lA[mt];
        float inv1 = 1.f / lB[mt];
        float* y0 = g_y + (size_t)(b * L_SEQ + rg0[mt]) * C_DIM + h * DH;
        float* y1 = g_y + (size_t)(b * L_SEQ + rg1[mt]) * C_DIM + h * DH;
#pragma unroll
        for (int nt = 0; nt < 8; nt++) {
            int c = nt * 8 + 2 * tig;
            *reinterpret_cast<float2*>(y0 + c) =
                make_float2(Oa[mt][nt][0] * inv0, Oa[mt][nt][1] * inv0);
            *reinterpret_cast<float2*>(y1 + c) =
                make_float2(Oa[mt][nt][2] * inv1, Oa[mt][nt][3] * inv1);
        }
    }
}

// ---------------------------------------------------------------------------
// Launch
// ---------------------------------------------------------------------------
extern "C" void kernel_launch(void* const* d_in, const int* in_sizes, int n_in,
                              void* d_out, int out_size) {
    const float*         x    = (const float*)d_in[0];
    const unsigned char* pad  = (const unsigned char*)d_in[1];
    const float*         Wqkv = (const float*)d_in[2];
    const float*         bqkv = (const float*)d_in[3];
    const float*         Wout = (const float*)d_in[4];
    const float*         bout = (const float*)d_in[5];
    float*               out  = (float*)d_out;

    cudaFuncSetAttribute(flash_attn_kernel,
                         cudaFuncAttributeMaxDynamicSharedMemorySize, FA_SMEM);

    rope_table_kernel<<<(L_SEQ * 32 + 255) / 256, 256>>>(pad);

    dim3 g1(N_QKV / 128, M_ROWS / 128);
    qkv_gemm_kernel<<<g1, 256>>>(x, Wqkv, bqkv);

    dim3 gr(L_SEQ / 64, BH_NUM);
    rope_transpose_kernel<<<gr, 256>>>();

    dim3 ga(L_SEQ / 128, BH_NUM);
    flash_attn_kernel<<<ga, 128, FA_SMEM>>>();

    dim3 g2(C_DIM / 128, M_ROWS / 128);
    out_gemm_kernel<<<g2, 256>>>(Wout, bout, out);
}

// round 14
// speedup vs baseline: 1.1291x; 1.0472x over previous
#include <cuda_runtime.h>
#include <cuda_bf16.h>
#include <math.h>

// Problem constants
#define B_SZ   4
#define L_SEQ  2048
#define C_DIM  1024
#define H_NUM  16
#define DH     64
#define M_ROWS (B_SZ * L_SEQ)          // 8192
#define N_QKV  (3 * C_DIM)             // 3072
#define BH_NUM (B_SZ * H_NUM)          // 64

// ---------------------------------------------------------------------------
// Static device scratch
// ---------------------------------------------------------------------------
__device__ float g_qkv[M_ROWS * N_QKV];              // (B*L, 3C) fp32
__device__ float g_q [BH_NUM * L_SEQ * DH];          // (bh,l,d) tf32 BITS, pre-scaled
__device__ float g_kT[BH_NUM * DH * L_SEQ];          // (bh,d,L) fp32
__device__ float g_y[M_ROWS * C_DIM];                // (B*L, C) tf32 BITS
__device__ float g_xc[M_ROWS * C_DIM];               // x tf32 BITS
__device__ float g_wqkv[C_DIM * N_QKV];              // W_qkv tf32 BITS
__device__ float g_wout[C_DIM * C_DIM];              // W_out tf32 BITS
__device__ float g_cs[L_SEQ][32];                    // RoPE cos table
__device__ float g_sn[L_SEQ][32];                    // RoPE sin table
__device__ float g_pb[M_ROWS];                       // pad bias (0 or -1e30)

// ---------------------------------------------------------------------------
// helpers
// ---------------------------------------------------------------------------
__device__ __forceinline__ unsigned f2tf(float f) {
    unsigned u;
    asm("cvt.rna.tf32.f32 %0, %1;" : "=r"(u) : "f"(f));
    return u;
}

__device__ __forceinline__ void mma_tf32(float* c, const unsigned* a, const unsigned* b) {
    asm("mma.sync.aligned.m16n8k8.row.col.f32.tf32.tf32.f32 "
        "{%0,%1,%2,%3}, {%4,%5,%6,%7}, {%8,%9}, {%0,%1,%2,%3};"
        : "+f"(c[0]), "+f"(c[1]), "+f"(c[2]), "+f"(c[3])
        : "r"(a[0]), "r"(a[1]), "r"(a[2]), "r"(a[3]), "r"(b[0]), "r"(b[1]));
}

__device__ __forceinline__ unsigned smaddr(const void* p) {
    return (unsigned)__cvta_generic_to_shared(p);
}

#define CP_ASYNC16(dst_u32, src) \
    asm volatile("cp.async.cg.shared.global [%0], [%1], 16;" :: "r"(dst_u32), "l"(src))
#define CP_COMMIT() asm volatile("cp.async.commit_group;")
#define CP_WAIT0()  asm volatile("cp.async.wait_group 0;" ::: "memory")

// ---------------------------------------------------------------------------
// Pre-convert fp32 -> tf32 bits (RNA), vectorized grid-stride
// ---------------------------------------------------------------------------
__global__ __launch_bounds__(256)
void tf32_convert_kernel(const float* __restrict__ src,
                         float* __restrict__ dst, int n4) {
    int i = blockIdx.x * 256 + threadIdx.x;
    int stride = gridDim.x * 256;
    for (; i < n4; i += stride) {
        float4 v = reinterpret_cast<const float4*>(src)[i];
        uint4 u = make_uint4(f2tf(v.x), f2tf(v.y), f2tf(v.z), f2tf(v.w));
        reinterpret_cast<uint4*>(dst)[i] = u;
    }
}

// ---------------------------------------------------------------------------
// tf32 GEMM + bias; A and B are PRE-CONVERTED tf32 bits -> no cvt in loop.
// ---------------------------------------------------------------------------
#define AS_STRIDE 20
#define BS_STRIDE 136

__device__ __forceinline__ void gemm_tc_body(const float* __restrict__ A,
                                             const float* __restrict__ Bm,
                                             const float* __restrict__ bias,
                                             float* __restrict__ C,
                                             int N, int K, bool cvt_out) {
    __shared__ float As[2][128 * AS_STRIDE];
    __shared__ float Bs[2][16 * BS_STRIDE];

    const int tid  = threadIdx.x;
    const int lane = tid & 31;
    const int wid  = tid >> 5;
    const int warp_m = wid & 1;
    const int warp_n = wid >> 1;
    const int grp = lane >> 2;
    const int tig = lane & 3;

    const int rowBlock = blockIdx.y * 128;
    const int colBlock = blockIdx.x * 128;
    const float* Abase = A + (size_t)rowBlock * K;

    float acc[4][4][4];
#pragma unroll
    for (int mt = 0; mt < 4; mt++)
#pragma unroll
        for (int nt = 0; nt < 4; nt++)
#pragma unroll
            for (int r = 0; r < 4; r++) acc[mt][nt][r] = 0.f;

    const int nk = K >> 4;

#pragma unroll
    for (int p = 0; p < 2; p++) {
        int c = p * 256 + tid;
        int row = c >> 2, k4 = (c & 3) * 4;
        CP_ASYNC16(smaddr(&As[0][row * AS_STRIDE + k4]),
                   Abase + (size_t)row * K + k4);
        int kr = c >> 5, n4 = (c & 31) * 4;
        CP_ASYNC16(smaddr(&Bs[0][kr * BS_STRIDE + n4]),
                   Bm + (size_t)kr * N + colBlock + n4);
    }
    CP_COMMIT();

    for (int kc = 0; kc < nk; kc++) {
        const int buf = kc & 1;
        CP_WAIT0();
        __syncthreads();

        if (kc + 1 < nk) {
            const int nb = buf ^ 1;
            const int kof = (kc + 1) * 16;
#pragma unroll
            for (int p = 0; p < 2; p++) {
                int c = p * 256 + tid;
                int row = c >> 2, k4 = (c & 3) * 4;
                CP_ASYNC16(smaddr(&As[nb][row * AS_STRIDE + k4]),
                           Abase + (size_t)row * K + kof + k4);
                int kr = c >> 5, n4 = (c & 31) * 4;
                CP_ASYNC16(smaddr(&Bs[nb][kr * BS_STRIDE + n4]),
                           Bm + (size_t)(kof + kr) * N + colBlock + n4);
            }
            CP_COMMIT();
        }

        const float* Ab = As[buf];
        const float* Bb = Bs[buf];
#pragma unroll
        for (int kk = 0; kk < 16; kk += 8) {
            unsigned af[4][4];
#pragma unroll
            for (int mt = 0; mt < 4; mt++) {
                int r0 = (warp_m * 64 + mt * 16 + grp) * AS_STRIDE + kk + tig;
                af[mt][0] = __float_as_uint(Ab[r0]);
                af[mt][1] = __float_as_uint(Ab[r0 + 8 * AS_STRIDE]);
                af[mt][2] = __float_as_uint(Ab[r0 + 4]);
                af[mt][3] = __float_as_uint(Ab[r0 + 8 * AS_STRIDE + 4]);
            }
            unsigned bf[4][2];
#pragma unroll
            for (int nt = 0; nt < 4; nt++) {
                int c0 = (kk + tig) * BS_STRIDE + warp_n * 32 + nt * 8 + grp;
                bf[nt][0] = __float_as_uint(Bb[c0]);
                bf[nt][1] = __float_as_uint(Bb[c0 + 4 * BS_STRIDE]);
            }
#pragma unroll
            for (int mt = 0; mt < 4; mt++)
#pragma unroll
                for (int nt = 0; nt < 4; nt++)
                    mma_tf32(acc[mt][nt], af[mt], bf[nt]);
        }
        __syncthreads();
    }

#pragma unroll
    for (int nt = 0; nt < 4; nt++) {
        int col = colBlock + warp_n * 32 + nt * 8 + tig * 2;
        float bx = bias[col], by = bias[col + 1];
#pragma unroll
        for (int mt = 0; mt < 4; mt++) {
            int row = rowBlock + warp_m * 64 + mt * 16 + grp;
            float2 r0 = make_float2(acc[mt][nt][0] + bx, acc[mt][nt][1] + by);
            float2 r1 = make_float2(acc[mt][nt][2] + bx, acc[mt][nt][3] + by);
            *reinterpret_cast<float2*>(C + (size_t)row * N + col) = r0;
            *reinterpret_cast<float2*>(C + (size_t)(row + 8) * N + col) = r1;
        }
    }
    (void)cvt_out;
}

__global__ __launch_bounds__(256)
void qkv_gemm_kernel(const float* __restrict__ b) {
    gemm_tc_body(g_xc, g_wqkv, b, g_qkv, N_QKV, C_DIM, false);
}

__global__ __launch_bounds__(256)
void out_gemm_kernel(const float* __restrict__ b,
                     float* __restrict__ out) {
    gemm_tc_body(g_y, g_wout, b, out, C_DIM, C_DIM, false);
}

// ---------------------------------------------------------------------------
// RoPE sin/cos table + pad bias
// ---------------------------------------------------------------------------
__global__ __launch_bounds__(256)
void rope_table_kernel(const unsigned char* __restrict__ pad) {
    int idx = blockIdx.x * 256 + threadIdx.x;
    if (idx < M_ROWS)
        g_pb[idx] = pad[idx] ? -1e30f : 0.f;
    if (idx >= L_SEQ * 32) return;
    int fi = idx & 31;
    int l  = idx >> 5;
    double invd = exp((double)fi * -0.28782313662425565);
    double ang  = (double)l * invd;
    g_cs[l][fi] = (float)cos(ang);
    g_sn[l][fi] = (float)sin(ang);
}

// ---------------------------------------------------------------------------
// RoPE: Q -> g_q (bh,l,d) tf32 BITS pre-scaled by 0.125*log2(e);
//       K -> g_kT (bh,d,L) fp32 transposed.
// ---------------------------------------------------------------------------
#define QK_SCALE 0.18033688011112042f   // 0.125 * log2(e)

__global__ __launch_bounds__(256)
void rope_transpose_kernel() {
    __shared__ float Tk[DH][65];

    const int tid = threadIdx.x;
    const int l0 = blockIdx.x * 64;
    const int bh = blockIdx.y;
    const int b  = bh >> 4;
    const int h  = bh & 15;

    float* qout = g_q + (size_t)bh * L_SEQ * DH;

#pragma unroll
    for (int p = 0; p < 16; p++) {
        int e = p * 256 + tid;
        int l = e >> 6;
        int d = e & 63;
        int row  = b * L_SEQ + l0 + l;
        int base = row * N_QKV + h * DH;

        float qv = g_qkv[base + d];
        float kv = g_qkv[base + C_DIM + d];
        int d2 = (d < 32) ? d + 32 : d - 32;
        float qr = (d < 32) ? -g_qkv[base + d2] : g_qkv[base + d2];
        float kr = (d < 32) ? -g_qkv[base + C_DIM + d2] : g_qkv[base + C_DIM + d2];

        float cs = g_cs[l0 + l][d & 31];
        float sn = g_sn[l0 + l][d & 31];

        float qrot = fmaf(qv, cs, qr * sn) * QK_SCALE;
        qout[(l0 + l) * DH + d] = __uint_as_float(f2tf(qrot));   // tf32 bits
        Tk[d][l] = fmaf(kv, cs, kr * sn);
    }
    __syncthreads();

    float* kout = g_kT + (size_t)bh * DH * L_SEQ;
#pragma unroll
    for (int p = 0; p < 16; p++) {
        int e = p * 256 + tid;
        int d = e >> 6;
        int l = e & 63;
        kout[d * L_SEQ + l0 + l] = Tk[d][l];
    }
}

// ---------------------------------------------------------------------------
// Tensor-core flash attention (R8 structure, epilogue writes tf32 bits).
// ---------------------------------------------------------------------------
#define SD 68
#define KV_WORDS (64 * SD)
#define Q_WORDS  (128 * SD)
#define FA_SMEM  ((Q_WORDS + 4 * KV_WORDS) * 4)    // 104448 bytes

__global__ __launch_bounds__(128)
void flash_attn_kernel() {
    extern __shared__ float sm[];
    float* Qs  = sm;
    float* Ks  = sm + Q_WORDS;
    float* Vsm = Ks + 2 * KV_WORDS;

    const int tid  = threadIdx.x;
    const int lane = tid & 31;
    const int wid  = tid >> 5;
    const int grp  = lane >> 2;
    const int tig  = lane & 3;

    const int qtb = (gridDim.x - 1) - blockIdx.x;
    const int bh  = blockIdx.y;
    const int b   = bh >> 4;
    const int h   = bh & 15;
    const int q0  = qtb * 128;

    const float* qgbase = g_q  + ((size_t)bh * L_SEQ + q0) * DH;
    const float* kbase  = g_kT + (size_t)bh * DH * L_SEQ;
    const float* vgbase = g_qkv + (size_t)b * L_SEQ * N_QKV + 2 * C_DIM + h * DH;
    const float* pb     = g_pb + b * L_SEQ;

#pragma unroll
    for (int p = 0; p < 16; p++) {
        int c = p * 128 + tid;
        int row = c >> 4, c4 = (c & 15) * 4;
        CP_ASYNC16(smaddr(&Qs[row * SD + c4]), qgbase + (size_t)row * DH + c4);
    }
#pragma unroll
    for (int p = 0; p < 8; p++) {
        int i = p * 128 + tid;
        int row = i >> 4, c4 = (i & 15) * 4;
        CP_ASYNC16(smaddr(&Ks[row * SD + c4]), kbase + (size_t)row * L_SEQ + c4);
        CP_ASYNC16(smaddr(&Vsm[row * SD + c4]), vgbase + (size_t)row * N_QKV + c4);
    }
    CP_COMMIT();

    float Oa[2][8][4];
#pragma unroll
    for (int mt = 0; mt < 2; mt++)
#pragma unroll
        for (int nt = 0; nt < 8; nt++)
#pragma unroll
            for (int r = 0; r < 4; r++) Oa[mt][nt][r] = 0.f;
    float mA[2] = {-INFINITY, -INFINITY};
    float mB[2] = {-INFINITY, -INFINITY};
    float lA[2] = {0.f, 0.f};
    float lB[2] = {0.f, 0.f};

    int rg0[2], rg1[2];
#pragma unroll
    for (int mt = 0; mt < 2; mt++) {
        rg0[mt] = q0 + wid * 32 + mt * 16 + grp;
        rg1[mt] = rg0[mt] + 8;
    }
    const int qrow_loc0 = wid * 32;

    const int psrc0 = (grp << 2) | (tig >> 1);
    const int psrc1 = psrc0 + 2;
    const bool podd = (tig & 1);

    const int nkt = 2 * qtb + 2;

    for (int kt = 0; kt < nkt; kt++) {
        const int k0  = kt * 64;
        const int buf = kt & 1;

        CP_WAIT0();
        __syncthreads();

        if (kt + 1 < nkt) {
            const int nb = buf ^ 1;
            const int nk0 = k0 + 64;
#pragma unroll
            for (int p = 0; p < 8; p++) {
                int i = p * 128 + tid;
                int row = i >> 4, c4 = (i & 15) * 4;
                CP_ASYNC16(smaddr(&Ks[nb * KV_WORDS + row * SD + c4]),
                           kbase + (size_t)row * L_SEQ + nk0 + c4);
                CP_ASYNC16(smaddr(&Vsm[nb * KV_WORDS + row * SD + c4]),
                           vgbase + (size_t)(nk0 + row) * N_QKV + c4);
            }
            CP_COMMIT();
        }

        const float* Kb = Ks  + buf * KV_WORDS;
        const float* Vb = Vsm + buf * KV_WORDS;

        float sacc[2][8][4];
#pragma unroll
        for (int mt = 0; mt < 2; mt++)
#pragma unroll
            for (int nt = 0; nt < 8; nt++)
#pragma unroll
                for (int r = 0; r < 4; r++) sacc[mt][nt][r] = 0.f;

#pragma unroll
        for (int kc = 0; kc < 8; kc++) {
            unsigned bf[8][2];
#pragma unroll
            for (int nt = 0; nt < 8; nt++) {
                int c0 = (kc * 8 + tig) * SD + nt * 8 + grp;
                bf[nt][0] = __float_as_uint(Kb[c0]);
                bf[nt][1] = __float_as_uint(Kb[c0 + 4 * SD]);
            }
#pragma unroll
            for (int mt = 0; mt < 2; mt++) {
                int r0 = (qrow_loc0 + mt * 16 + grp) * SD + kc * 8 + tig;
                unsigned af[4];
                af[0] = __float_as_uint(Qs[r0]);
                af[1] = __float_as_uint(Qs[r0 + 8 * SD]);
                af[2] = __float_as_uint(Qs[r0 + 4]);
                af[3] = __float_as_uint(Qs[r0 + 8 * SD + 4]);
#pragma unroll
                for (int nt = 0; nt < 8; nt++)
                    mma_tf32(sacc[mt][nt], af, bf[nt]);
            }
        }

        const bool diag = (kt >= 2 * qtb);
#pragma unroll
        for (int mt = 0; mt < 2; mt++) {
            float mx0 = -INFINITY, mx1 = -INFINITY;
#pragma unroll
            for (int nt = 0; nt < 8; nt++) {
                int c = nt * 8 + 2 * tig;
                float2 pbv = *reinterpret_cast<const float2*>(&pb[k0 + c]);
                float s0 = sacc[mt][nt][0] + pbv.x;
                float s1 = sacc[mt][nt][1] + pbv.y;
                float s2 = sacc[mt][nt][2] + pbv.x;
                float s3 = sacc[mt][nt][3] + pbv.y;
                if (diag) {
                    int col0 = k0 + c, col1 = col0 + 1;
                    if (col0 > rg0[mt]) s0 = -1e30f;
                    if (col1 > rg0[mt]) s1 = -1e30f;
                    if (col0 > rg1[mt]) s2 = -1e30f;
                    if (col1 > rg1[mt]) s3 = -1e30f;
                }
                sacc[mt][nt][0] = s0; sacc[mt][nt][1] = s1;
                sacc[mt][nt][2] = s2; sacc[mt][nt][3] = s3;
                mx0 = fmaxf(mx0, fmaxf(s0, s1));
                mx1 = fmaxf(mx1, fmaxf(s2, s3));
            }
            mx0 = fmaxf(mx0, __shfl_xor_sync(0xffffffffu, mx0, 1));
            mx0 = fmaxf(mx0, __shfl_xor_sync(0xffffffffu, mx0, 2));
            mx1 = fmaxf(mx1, __shfl_xor_sync(0xffffffffu, mx1, 1));
            mx1 = fmaxf(mx1, __shfl_xor_sync(0xffffffffu, mx1, 2));

            float mn0 = fmaxf(mA[mt], mx0);
            float mn1 = fmaxf(mB[mt], mx1);
            float corr0 = exp2f(mA[mt] - mn0);
            float corr1 = exp2f(mB[mt] - mn1);
            mA[mt] = mn0; mB[mt] = mn1;

            float rs0 = 0.f, rs1 = 0.f;
#pragma unroll
            for (int nt = 0; nt < 8; nt++) {
                float p0 = exp2f(sacc[mt][nt][0] - mn0);
                float p1 = exp2f(sacc[mt][nt][1] - mn0);
                float p2 = exp2f(sacc[mt][nt][2] - mn1);
                float p3 = exp2f(sacc[mt][nt][3] - mn1);
                sacc[mt][nt][0] = p0; sacc[mt][nt][1] = p1;
                sacc[mt][nt][2] = p2; sacc[mt][nt][3] = p3;
                rs0 += p0 + p1;
                rs1 += p2 + p3;
            }
            rs0 += __shfl_xor_sync(0xffffffffu, rs0, 1);
            rs0 += __shfl_xor_sync(0xffffffffu, rs0, 2);
            rs1 += __shfl_xor_sync(0xffffffffu, rs1, 1);
            rs1 += __shfl_xor_sync(0xffffffffu, rs1, 2);
            lA[mt] = lA[mt] * corr0 + rs0;
            lB[mt] = lB[mt] * corr1 + rs1;
#pragma unroll
            for (int nt = 0; nt < 8; nt++) {
                Oa[mt][nt][0] *= corr0; Oa[mt][nt][1] *= corr0;
                Oa[mt][nt][2] *= corr1; Oa[mt][nt][3] *= corr1;
            }
        }

#pragma unroll
        for (int kc = 0; kc < 8; kc++) {
            unsigned bf[8][2];
#pragma unroll
            for (int nt = 0; nt < 8; nt++) {
                int c0 = (kc * 8 + tig) * SD + nt * 8 + grp;
                bf[nt][0] = __float_as_uint(Vb[c0]);
                bf[nt][1] = __float_as_uint(Vb[c0 + 4 * SD]);
            }
#pragma unroll
            for (int mt = 0; mt < 2; mt++) {
                float v0 = __shfl_sync(0xffffffffu, sacc[mt][kc][0], psrc0, 32);
                float v1 = __shfl_sync(0xffffffffu, sacc[mt][kc][1], psrc0, 32);
                float v2 = __shfl_sync(0xffffffffu, sacc[mt][kc][2], psrc0, 32);
                float v3 = __shfl_sync(0xffffffffu, sacc[mt][kc][3], psrc0, 32);
                float w0 = __shfl_sync(0xffffffffu, sacc[mt][kc][0], psrc1, 32);
                float w1 = __shfl_sync(0xffffffffu, sacc[mt][kc][1], psrc1, 32);
                float w2 = __shfl_sync(0xffffffffu, sacc[mt][kc][2], psrc1, 32);
                float w3 = __shfl_sync(0xffffffffu, sacc[mt][kc][3], psrc1, 32);
                unsigned af[4];
                af[0] = f2tf(podd ? v1 : v0);
                af[1] = f2tf(podd ? v3 : v2);
                af[2] = f2tf(podd ? w1 : w0);
                af[3] = f2tf(podd ? w3 : w2);
#pragma unroll
                for (int nt = 0; nt < 8; nt++)
                    mma_tf32(Oa[mt][nt], af, bf[nt]);
            }
        }
    }

    // ---- epilogue: write tf32 BITS (out_gemm A-side is pre-converted) ----
#pragma unroll
    for (int mt = 0; mt < 2; mt++) {
        float inv0 = 1.f / lA[mt];
        float inv1 = 1.f / lB[mt];
        float* y0 = g_y + (size_t)(b * L_SEQ + rg0[mt]) * C_DIM + h * DH;
        float* y1 = g_y + (size_t)(b * L_SEQ + rg1[mt]) * C_DIM + h * DH;
#pragma unroll
        for (int nt = 0; nt < 8; nt++) {
            int c = nt * 8 + 2 * tig;
            uint2 u0 = make_uint2(f2tf(Oa[mt][nt][0] * inv0), f2tf(Oa[mt][nt][1] * inv0));
            uint2 u1 = make_uint2(f2tf(Oa[mt][nt][2] * inv1), f2tf(Oa[mt][nt][3] * inv1));
            *reinterpret_cast<uint2*>(y0 + c) = u0;
            *reinterpret_cast<uint2*>(y1 + c) = u1;
        }
    }
}

// ---------------------------------------------------------------------------
// Launch
// ---------------------------------------------------------------------------
extern "C" void kernel_launch(void* const* d_in, const int* in_sizes, int n_in,
                              void* d_out, int out_size) {
    const float*         x    = (const float*)d_in[0];
    const unsigned char* pad  = (const unsigned char*)d_in[1];
    const float*         Wqkv = (const float*)d_in[2];
    const float*         bqkv = (const float*)d_in[3];
    const float*         Wout = (const float*)d_in[4];
    const float*         bout = (const float*)d_in[5];
    float*               out  = (float*)d_out;

    cudaFuncSetAttribute(flash_attn_kernel,
                         cudaFuncAttributeMaxDynamicSharedMemorySize, FA_SMEM);

    // device-global targets for the convert kernels
    float *p_xc, *p_wqkv, *p_wout;
    cudaGetSymbolAddress((void**)&p_xc,   g_xc);
    cudaGetSymbolAddress((void**)&p_wqkv, g_wqkv);
    cudaGetSymbolAddress((void**)&p_wout, g_wout);

    rope_table_kernel<<<(L_SEQ * 32 + 255) / 256, 256>>>(pad);

    tf32_convert_kernel<<<592, 256>>>(x,    p_xc,   (M_ROWS * C_DIM) / 4);
    tf32_convert_kernel<<<592, 256>>>(Wqkv, p_wqkv, (C_DIM * N_QKV) / 4);
    tf32_convert_kernel<<<592, 256>>>(Wout, p_wout, (C_DIM * C_DIM) / 4);

    dim3 g1(N_QKV / 128, M_ROWS / 128);
    qkv_gemm_kernel<<<g1, 256>>>(bqkv);

    dim3 gr(L_SEQ / 64, BH_NUM);
    rope_transpose_kernel<<<gr, 256>>>();

    dim3 ga(L_SEQ / 128, BH_NUM);
    flash_attn_kernel<<<ga, 128, FA_SMEM>>>();

    dim3 g2(C_DIM / 128, M_ROWS / 128);
    out_gemm_kernel<<<g2, 256>>>(bout, out);
}

// round 16
// speedup vs baseline: 1.2385x; 1.0969x over previous
#include <cuda_runtime.h>
#include <cuda_bf16.h>
#include <math.h>

// Problem constants
#define B_SZ   4
#define L_SEQ  2048
#define C_DIM  1024
#define H_NUM  16
#define DH     64
#define M_ROWS (B_SZ * L_SEQ)          // 8192
#define N_QKV  (3 * C_DIM)             // 3072
#define BH_NUM (B_SZ * H_NUM)          // 64

// ---------------------------------------------------------------------------
// Static device scratch
// ---------------------------------------------------------------------------
__device__ float g_qkv[M_ROWS * N_QKV];              // (B*L, 3C) fp32
__device__ float g_q [BH_NUM * L_SEQ * DH];          // (bh,l,d) tf32 BITS, pre-scaled
__device__ float g_kT[BH_NUM * DH * L_SEQ];          // (bh,d,L) fp32
__device__ float g_y[M_ROWS * C_DIM];                // (B*L, C) tf32 BITS
__device__ float g_xc[M_ROWS * C_DIM];               // x tf32 BITS
__device__ float g_wqkv[C_DIM * N_QKV];              // W_qkv tf32 BITS
__device__ float g_wout[C_DIM * C_DIM];              // W_out tf32 BITS
__device__ float g_cs[L_SEQ][32];                    // RoPE cos table
__device__ float g_sn[L_SEQ][32];                    // RoPE sin table
__device__ float g_pb[M_ROWS];                       // pad bias (0 or -1e30)

// ---------------------------------------------------------------------------
// helpers
// ---------------------------------------------------------------------------
__device__ __forceinline__ unsigned f2tf(float f) {
    unsigned u;
    asm("cvt.rna.tf32.f32 %0, %1;" : "=r"(u) : "f"(f));
    return u;
}

__device__ __forceinline__ void mma_tf32(float* c, const unsigned* a, const unsigned* b) {
    asm("mma.sync.aligned.m16n8k8.row.col.f32.tf32.tf32.f32 "
        "{%0,%1,%2,%3}, {%4,%5,%6,%7}, {%8,%9}, {%0,%1,%2,%3};"
        : "+f"(c[0]), "+f"(c[1]), "+f"(c[2]), "+f"(c[3])
        : "r"(a[0]), "r"(a[1]), "r"(a[2]), "r"(a[3]), "r"(b[0]), "r"(b[1]));
}

__device__ __forceinline__ unsigned smaddr(const void* p) {
    return (unsigned)__cvta_generic_to_shared(p);
}

#define CP_ASYNC16(dst_u32, src) \
    asm volatile("cp.async.cg.shared.global [%0], [%1], 16;" :: "r"(dst_u32), "l"(src))
#define CP_COMMIT() asm volatile("cp.async.commit_group;")
#define CP_WAIT0()  asm volatile("cp.async.wait_group 0;" ::: "memory")

// ---------------------------------------------------------------------------
// Pre-convert fp32 -> tf32 bits (RNA), vectorized grid-stride
// ---------------------------------------------------------------------------
__global__ __launch_bounds__(256)
void tf32_convert_kernel(const float* __restrict__ src,
                         float* __restrict__ dst, int n4) {
    int i = blockIdx.x * 256 + threadIdx.x;
    int stride = gridDim.x * 256;
    for (; i < n4; i += stride) {
        float4 v = reinterpret_cast<const float4*>(src)[i];
        uint4 u = make_uint4(f2tf(v.x), f2tf(v.y), f2tf(v.z), f2tf(v.w));
        reinterpret_cast<uint4*>(dst)[i] = u;
    }
}

// ---------------------------------------------------------------------------
// tf32 GEMM + bias, BK=32, dynamic SMEM double-buffered.
// A,B pre-converted tf32 bits. 128x128 tile, 8 warps (2m x 4n), warp 64x32.
// ---------------------------------------------------------------------------
#define AS2 36    // 128 rows x (32+4); banks 4*grp+tig all-distinct
#define BS2 136   // 32 rows x (128+8)
#define GEMM_SMEM ((2 * 128 * AS2 + 2 * 32 * BS2) * 4)   // 71680 bytes

__device__ __forceinline__ void gemm_tc_body(const float* __restrict__ A,
                                             const float* __restrict__ Bm,
                                             const float* __restrict__ bias,
                                             float* __restrict__ C,
                                             int N, int K) {
    extern __shared__ float gsm[];
    float* As = gsm;                       // [2][128*AS2]
    float* Bs = gsm + 2 * 128 * AS2;       // [2][32*BS2]

    const int tid  = threadIdx.x;
    const int lane = tid & 31;
    const int wid  = tid >> 5;
    const int warp_m = wid & 1;
    const int warp_n = wid >> 1;
    const int grp = lane >> 2;
    const int tig = lane & 3;

    const int rowBlock = blockIdx.y * 128;
    const int colBlock = blockIdx.x * 128;
    const float* Abase = A + (size_t)rowBlock * K;

    float acc[4][4][4];
#pragma unroll
    for (int mt = 0; mt < 4; mt++)
#pragma unroll
        for (int nt = 0; nt < 4; nt++)
#pragma unroll
            for (int r = 0; r < 4; r++) acc[mt][nt][r] = 0.f;

    const int nk = K >> 5;                 // BK=32

    // ---- stage 0 ----
#pragma unroll
    for (int p = 0; p < 4; p++) {
        int c = p * 256 + tid;
        int row = c >> 3, k4 = (c & 7) * 4;               // A: 128x32
        CP_ASYNC16(smaddr(&As[row * AS2 + k4]),
                   Abase + (size_t)row * K + k4);
        int kr = c >> 5, n4 = (c & 31) * 4;               // B: 32x128
        CP_ASYNC16(smaddr(&Bs[kr * BS2 + n4]),
                   Bm + (size_t)kr * N + colBlock + n4);
    }
    CP_COMMIT();

    for (int kc = 0; kc < nk; kc++) {
        const int buf = kc & 1;
        CP_WAIT0();
        __syncthreads();

        if (kc + 1 < nk) {
            const int nb = buf ^ 1;
            const int kof = (kc + 1) * 32;
#pragma unroll
            for (int p = 0; p < 4; p++) {
                int c = p * 256 + tid;
                int row = c >> 3, k4 = (c & 7) * 4;
                CP_ASYNC16(smaddr(&As[nb * 128 * AS2 + row * AS2 + k4]),
                           Abase + (size_t)row * K + kof + k4);
                int kr = c >> 5, n4 = (c & 31) * 4;
                CP_ASYNC16(smaddr(&Bs[nb * 32 * BS2 + kr * BS2 + n4]),
                           Bm + (size_t)(kof + kr) * N + colBlock + n4);
            }
            CP_COMMIT();
        }

        const float* Ab = As + buf * 128 * AS2;
        const float* Bb = Bs + buf * 32 * BS2;
#pragma unroll
        for (int kk = 0; kk < 32; kk += 8) {
            unsigned af[4][4];
#pragma unroll
            for (int mt = 0; mt < 4; mt++) {
                int r0 = (warp_m * 64 + mt * 16 + grp) * AS2 + kk + tig;
                af[mt][0] = __float_as_uint(Ab[r0]);
                af[mt][1] = __float_as_uint(Ab[r0 + 8 * AS2]);
                af[mt][2] = __float_as_uint(Ab[r0 + 4]);
                af[mt][3] = __float_as_uint(Ab[r0 + 8 * AS2 + 4]);
            }
            unsigned bf[4][2];
#pragma unroll
            for (int nt = 0; nt < 4; nt++) {
                int c0 = (kk + tig) * BS2 + warp_n * 32 + nt * 8 + grp;
                bf[nt][0] = __float_as_uint(Bb[c0]);
                bf[nt][1] = __float_as_uint(Bb[c0 + 4 * BS2]);
            }
#pragma unroll
            for (int mt = 0; mt < 4; mt++)
#pragma unroll
                for (int nt = 0; nt < 4; nt++)
                    mma_tf32(acc[mt][nt], af[mt], bf[nt]);
        }
        __syncthreads();
    }

#pragma unroll
    for (int nt = 0; nt < 4; nt++) {
        int col = colBlock + warp_n * 32 + nt * 8 + tig * 2;
        float bx = bias[col], by = bias[col + 1];
#pragma unroll
        for (int mt = 0; mt < 4; mt++) {
            int row = rowBlock + warp_m * 64 + mt * 16 + grp;
            *reinterpret_cast<float2*>(C + (size_t)row * N + col) =
                make_float2(acc[mt][nt][0] + bx, acc[mt][nt][1] + by);
            *reinterpret_cast<float2*>(C + (size_t)(row + 8) * N + col) =
                make_float2(acc[mt][nt][2] + bx, acc[mt][nt][3] + by);
        }
    }
}

__global__ __launch_bounds__(256)
void qkv_gemm_kernel(const float* __restrict__ b) {
    gemm_tc_body(g_xc, g_wqkv, b, g_qkv, N_QKV, C_DIM);
}

__global__ __launch_bounds__(256)
void out_gemm_kernel(const float* __restrict__ b,
                     float* __restrict__ out) {
    gemm_tc_body(g_y, g_wout, b, out, C_DIM, C_DIM);
}

// ---------------------------------------------------------------------------
// RoPE sin/cos table + pad bias
// ---------------------------------------------------------------------------
__global__ __launch_bounds__(256)
void rope_table_kernel(const unsigned char* __restrict__ pad) {
    int idx = blockIdx.x * 256 + threadIdx.x;
    if (idx < M_ROWS)
        g_pb[idx] = pad[idx] ? -1e30f : 0.f;
    if (idx >= L_SEQ * 32) return;
    int fi = idx & 31;
    int l  = idx >> 5;
    double invd = exp((double)fi * -0.28782313662425565);
    double ang  = (double)l * invd;
    g_cs[l][fi] = (float)cos(ang);
    g_sn[l][fi] = (float)sin(ang);
}

// ---------------------------------------------------------------------------
// RoPE (vectorized, pair-fused): each thread handles float4 lower + upper half.
//  Q -> g_q (bh,l,d) tf32 BITS pre-scaled by 0.125*log2(e)
//  K -> g_kT (bh,d,L) fp32 transposed
// ---------------------------------------------------------------------------
#define QK_SCALE 0.18033688011112042f   // 0.125 * log2(e)

__global__ __launch_bounds__(256)
void rope_transpose_kernel() {
    __shared__ float Tk[DH][65];

    const int tid = threadIdx.x;
    const int l0 = blockIdx.x * 64;
    const int bh = blockIdx.y;
    const int b  = bh >> 4;
    const int h  = bh & 15;

    float* qout = g_q + (size_t)bh * L_SEQ * DH;

    // 64 l x 8 float4-pairs = 512 units, 2 per thread
#pragma unroll
    for (int p = 0; p < 2; p++) {
        int e = p * 256 + tid;
        int l  = e >> 3;             // 0..63
        int d4 = (e & 7) * 4;        // 0,4,...,28 (lower half)
        int gl = l0 + l;
        const float* rowp = g_qkv + (size_t)(b * L_SEQ + gl) * N_QKV + h * DH;

        float4 qlo = *reinterpret_cast<const float4*>(rowp + d4);
        float4 qhi = *reinterpret_cast<const float4*>(rowp + d4 + 32);
        float4 klo = *reinterpret_cast<const float4*>(rowp + C_DIM + d4);
        float4 khi = *reinterpret_cast<const float4*>(rowp + C_DIM + d4 + 32);
        float4 cs  = *reinterpret_cast<const float4*>(&g_cs[gl][d4]);
        float4 sn  = *reinterpret_cast<const float4*>(&g_sn[gl][d4]);

        // lower: x*cos - x_hi*sin ; upper: x*cos + x_lo*sin
        float4 qol = make_float4(fmaf(qlo.x, cs.x, -qhi.x * sn.x),
                                 fmaf(qlo.y, cs.y, -qhi.y * sn.y),
                                 fmaf(qlo.z, cs.z, -qhi.z * sn.z),
                                 fmaf(qlo.w, cs.w, -qhi.w * sn.w));
        float4 qoh = make_float4(fmaf(qhi.x, cs.x, qlo.x * sn.x),
                                 fmaf(qhi.y, cs.y, qlo.y * sn.y),
                                 fmaf(qhi.z, cs.z, qlo.z * sn.z),
                                 fmaf(qhi.w, cs.w, qlo.w * sn.w));
        float4 kol = make_float4(fmaf(klo.x, cs.x, -khi.x * sn.x),
                                 fmaf(klo.y, cs.y, -khi.y * sn.y),
                                 fmaf(klo.z, cs.z, -khi.z * sn.z),
                                 fmaf(klo.w, cs.w, -khi.w * sn.w));
        float4 koh = make_float4(fmaf(khi.x, cs.x, klo.x * sn.x),
                                 fmaf(khi.y, cs.y, klo.y * sn.y),
                                 fmaf(khi.z, cs.z, klo.z * sn.z),
                                 fmaf(khi.w, cs.w, klo.w * sn.w));

        uint4 ql = make_uint4(f2tf(qol.x * QK_SCALE), f2tf(qol.y * QK_SCALE),
                              f2tf(qol.z * QK_SCALE), f2tf(qol.w * QK_SCALE));
        uint4 qh = make_uint4(f2tf(qoh.x * QK_SCALE), f2tf(qoh.y * QK_SCALE),
                              f2tf(qoh.z * QK_SCALE), f2tf(qoh.w * QK_SCALE));
        *reinterpret_cast<uint4*>(qout + (size_t)gl * DH + d4)      = ql;
        *reinterpret_cast<uint4*>(qout + (size_t)gl * DH + d4 + 32) = qh;

        Tk[d4 + 0][l] = kol.x;  Tk[d4 + 1][l] = kol.y;
        Tk[d4 + 2][l] = kol.z;  Tk[d4 + 3][l] = kol.w;
        Tk[d4 + 32][l] = koh.x; Tk[d4 + 33][l] = koh.y;
        Tk[d4 + 34][l] = koh.z; Tk[d4 + 35][l] = koh.w;
    }
    __syncthreads();

    // transposed writeout, float4 over l
    float* kout = g_kT + (size_t)bh * DH * L_SEQ;
#pragma unroll
    for (int p = 0; p < 4; p++) {
        int e = p * 256 + tid;
        int d  = e >> 4;
        int l4 = (e & 15) * 4;
        float4 v = make_float4(Tk[d][l4], Tk[d][l4 + 1], Tk[d][l4 + 2], Tk[d][l4 + 3]);
        *reinterpret_cast<float4*>(kout + (size_t)d * L_SEQ + l0 + l4) = v;
    }
}

// ---------------------------------------------------------------------------
// Tensor-core flash attention (R8 structure, unchanged).
// ---------------------------------------------------------------------------
#define SD 68
#define KV_WORDS (64 * SD)
#define Q_WORDS  (128 * SD)
#define FA_SMEM  ((Q_WORDS + 4 * KV_WORDS) * 4)    // 104448 bytes

__global__ __launch_bounds__(128)
void flash_attn_kernel() {
    extern __shared__ float sm[];
    float* Qs  = sm;
    float* Ks  = sm + Q_WORDS;
    float* Vsm = Ks + 2 * KV_WORDS;

    const int tid  = threadIdx.x;
    const int lane = tid & 31;
    const int wid  = tid >> 5;
    const int grp  = lane >> 2;
    const int tig  = lane & 3;

    const int qtb = (gridDim.x - 1) - blockIdx.x;
    const int bh  = blockIdx.y;
    const int b   = bh >> 4;
    const int h   = bh & 15;
    const int q0  = qtb * 128;

    const float* qgbase = g_q  + ((size_t)bh * L_SEQ + q0) * DH;
    const float* kbase  = g_kT + (size_t)bh * DH * L_SEQ;
    const float* vgbase = g_qkv + (size_t)b * L_SEQ * N_QKV + 2 * C_DIM + h * DH;
    const float* pb     = g_pb + b * L_SEQ;

#pragma unroll
    for (int p = 0; p < 16; p++) {
        int c = p * 128 + tid;
        int row = c >> 4, c4 = (c & 15) * 4;
        CP_ASYNC16(smaddr(&Qs[row * SD + c4]), qgbase + (size_t)row * DH + c4);
    }
#pragma unroll
    for (int p = 0; p < 8; p++) {
        int i = p * 128 + tid;
        int row = i >> 4, c4 = (i & 15) * 4;
        CP_ASYNC16(smaddr(&Ks[row * SD + c4]), kbase + (size_t)row * L_SEQ + c4);
        CP_ASYNC16(smaddr(&Vsm[row * SD + c4]), vgbase + (size_t)row * N_QKV + c4);
    }
    CP_COMMIT();

    float Oa[2][8][4];
#pragma unroll
    for (int mt = 0; mt < 2; mt++)
#pragma unroll
        for (int nt = 0; nt < 8; nt++)
#pragma unroll
            for (int r = 0; r < 4; r++) Oa[mt][nt][r] = 0.f;
    float mA[2] = {-INFINITY, -INFINITY};
    float mB[2] = {-INFINITY, -INFINITY};
    float lA[2] = {0.f, 0.f};
    float lB[2] = {0.f, 0.f};

    int rg0[2], rg1[2];
#pragma unroll
    for (int mt = 0; mt < 2; mt++) {
        rg0[mt] = q0 + wid * 32 + mt * 16 + grp;
        rg1[mt] = rg0[mt] + 8;
    }
    const int qrow_loc0 = wid * 32;

    const int psrc0 = (grp << 2) | (tig >> 1);
    const int psrc1 = psrc0 + 2;
    const bool podd = (tig & 1);

    const int nkt = 2 * qtb + 2;

    for (int kt = 0; kt < nkt; kt++) {
        const int k0  = kt * 64;
        const int buf = kt & 1;

        CP_WAIT0();
        __syncthreads();

        if (kt + 1 < nkt) {
            const int nb = buf ^ 1;
            const int nk0 = k0 + 64;
#pragma unroll
            for (int p = 0; p < 8; p++) {
                int i = p * 128 + tid;
                int row = i >> 4, c4 = (i & 15) * 4;
                CP_ASYNC16(smaddr(&Ks[nb * KV_WORDS + row * SD + c4]),
                           kbase + (size_t)row * L_SEQ + nk0 + c4);
                CP_ASYNC16(smaddr(&Vsm[nb * KV_WORDS + row * SD + c4]),
                           vgbase + (size_t)(nk0 + row) * N_QKV + c4);
            }
            CP_COMMIT();
        }

        const float* Kb = Ks  + buf * KV_WORDS;
        const float* Vb = Vsm + buf * KV_WORDS;

        float sacc[2][8][4];
#pragma unroll
        for (int mt = 0; mt < 2; mt++)
#pragma unroll
            for (int nt = 0; nt < 8; nt++)
#pragma unroll
                for (int r = 0; r < 4; r++) sacc[mt][nt][r] = 0.f;

#pragma unroll
        for (int kc = 0; kc < 8; kc++) {
            unsigned bf[8][2];
#pragma unroll
            for (int nt = 0; nt < 8; nt++) {
                int c0 = (kc * 8 + tig) * SD + nt * 8 + grp;
                bf[nt][0] = __float_as_uint(Kb[c0]);
                bf[nt][1] = __float_as_uint(Kb[c0 + 4 * SD]);
            }
#pragma unroll
            for (int mt = 0; mt < 2; mt++) {
                int r0 = (qrow_loc0 + mt * 16 + grp) * SD + kc * 8 + tig;
                unsigned af[4];
                af[0] = __float_as_uint(Qs[r0]);
                af[1] = __float_as_uint(Qs[r0 + 8 * SD]);
                af[2] = __float_as_uint(Qs[r0 + 4]);
                af[3] = __float_as_uint(Qs[r0 + 8 * SD + 4]);
#pragma unroll
                for (int nt = 0; nt < 8; nt++)
                    mma_tf32(sacc[mt][nt], af, bf[nt]);
            }
        }

        const bool diag = (kt >= 2 * qtb);
#pragma unroll
        for (int mt = 0; mt < 2; mt++) {
            float mx0 = -INFINITY, mx1 = -INFINITY;
#pragma unroll
            for (int nt = 0; nt < 8; nt++) {
                int c = nt * 8 + 2 * tig;
                float2 pbv = *reinterpret_cast<const float2*>(&pb[k0 + c]);
                float s0 = sacc[mt][nt][0] + pbv.x;
                float s1 = sacc[mt][nt][1] + pbv.y;
                float s2 = sacc[mt][nt][2] + pbv.x;
                float s3 = sacc[mt][nt][3] + pbv.y;
                if (diag) {
                    int col0 = k0 + c, col1 = col0 + 1;
                    if (col0 > rg0[mt]) s0 = -1e30f;
                    if (col1 > rg0[mt]) s1 = -1e30f;
                    if (col0 > rg1[mt]) s2 = -1e30f;
                    if (col1 > rg1[mt]) s3 = -1e30f;
                }
                sacc[mt][nt][0] = s0; sacc[mt][nt][1] = s1;
                sacc[mt][nt][2] = s2; sacc[mt][nt][3] = s3;
                mx0 = fmaxf(mx0, fmaxf(s0, s1));
                mx1 = fmaxf(mx1, fmaxf(s2, s3));
            }
            mx0 = fmaxf(mx0, __shfl_xor_sync(0xffffffffu, mx0, 1));
            mx0 = fmaxf(mx0, __shfl_xor_sync(0xffffffffu, mx0, 2));
            mx1 = fmaxf(mx1, __shfl_xor_sync(0xffffffffu, mx1, 1));
            mx1 = fmaxf(mx1, __shfl_xor_sync(0xffffffffu, mx1, 2));

            float mn0 = fmaxf(mA[mt], mx0);
            float mn1 = fmaxf(mB[mt], mx1);
            float corr0 = exp2f(mA[mt] - mn0);
            float corr1 = exp2f(mB[mt] - mn1);
            mA[mt] = mn0; mB[mt] = mn1;

            float rs0 = 0.f, rs1 = 0.f;
#pragma unroll
            for (int nt = 0; nt < 8; nt++) {
                float p0 = exp2f(sacc[mt][nt][0] - mn0);
                float p1 = exp2f(sacc[mt][nt][1] - mn0);
                float p2 = exp2f(sacc[mt][nt][2] - mn1);
                float p3 = exp2f(sacc[mt][nt][3] - mn1);
                sacc[mt][nt][0] = p0; sacc[mt][nt][1] = p1;
                sacc[mt][nt][2] = p2; sacc[mt][nt][3] = p3;
                rs0 += p0 + p1;
                rs1 += p2 + p3;
            }
            rs0 += __shfl_xor_sync(0xffffffffu, rs0, 1);
            rs0 += __shfl_xor_sync(0xffffffffu, rs0, 2);
            rs1 += __shfl_xor_sync(0xffffffffu, rs1, 1);
            rs1 += __shfl_xor_sync(0xffffffffu, rs1, 2);
            lA[mt] = lA[mt] * corr0 + rs0;
            lB[mt] = lB[mt] * corr1 + rs1;
#pragma unroll
            for (int nt = 0; nt < 8; nt++) {
                Oa[mt][nt][0] *= corr0; Oa[mt][nt][1] *= corr0;
                Oa[mt][nt][2] *= corr1; Oa[mt][nt][3] *= corr1;
            }
        }

#pragma unroll
        for (int kc = 0; kc < 8; kc++) {
            unsigned bf[8][2];
#pragma unroll
            for (int nt = 0; nt < 8; nt++) {
                int c0 = (kc * 8 + tig) * SD + nt * 8 + grp;
                bf[nt][0] = __float_as_uint(Vb[c0]);
                bf[nt][1] = __float_as_uint(Vb[c0 + 4 * SD]);
            }
#pragma unroll
            for (int mt = 0; mt < 2; mt++) {
                float v0 = __shfl_sync(0xffffffffu, sacc[mt][kc][0], psrc0, 32);
                float v1 = __shfl_sync(0xffffffffu, sacc[mt][kc][1], psrc0, 32);
                float v2 = __shfl_sync(0xffffffffu, sacc[mt][kc][2], psrc0, 32);
                float v3 = __shfl_sync(0xffffffffu, sacc[mt][kc][3], psrc0, 32);
                float w0 = __shfl_sync(0xffffffffu, sacc[mt][kc][0], psrc1, 32);
                float w1 = __shfl_sync(0xffffffffu, sacc[mt][kc][1], psrc1, 32);
                float w2 = __shfl_sync(0xffffffffu, sacc[mt][kc][2], psrc1, 32);
                float w3 = __shfl_sync(0xffffffffu, sacc[mt][kc][3], psrc1, 32);
                unsigned af[4];
                af[0] = f2tf(podd ? v1 : v0);
                af[1] = f2tf(podd ? v3 : v2);
                af[2] = f2tf(podd ? w1 : w0);
                af[3] = f2tf(podd ? w3 : w2);
#pragma unroll
                for (int nt = 0; nt < 8; nt++)
                    mma_tf32(Oa[mt][nt], af, bf[nt]);
            }
        }
    }

    // ---- epilogue: write tf32 BITS ----
#pragma unroll
    for (int mt = 0; mt < 2; mt++) {
        float inv0 = 1.f / lA[mt];
        float inv1 = 1.f / lB[mt];
        float* y0 = g_y + (size_t)(b * L_SEQ + rg0[mt]) * C_DIM + h * DH;
        float* y1 = g_y + (size_t)(b * L_SEQ + rg1[mt]) * C_DIM + h * DH;
#pragma unroll
        for (int nt = 0; nt < 8; nt++) {
            int c = nt * 8 + 2 * tig;
            uint2 u0 = make_uint2(f2tf(Oa[mt][nt][0] * inv0), f2tf(Oa[mt][nt][1] * inv0));
            uint2 u1 = make_uint2(f2tf(Oa[mt][nt][2] * inv1), f2tf(Oa[mt][nt][3] * inv1));
            *reinterpret_cast<uint2*>(y0 + c) = u0;
            *reinterpret_cast<uint2*>(y1 + c) = u1;
        }
    }
}

// ---------------------------------------------------------------------------
// Launch
// ---------------------------------------------------------------------------
extern "C" void kernel_launch(void* const* d_in, const int* in_sizes, int n_in,
                              void* d_out, int out_size) {
    const float*         x    = (const float*)d_in[0];
    const unsigned char* pad  = (const unsigned char*)d_in[1];
    const float*         Wqkv = (const float*)d_in[2];
    const float*         bqkv = (const float*)d_in[3];
    const float*         Wout = (const float*)d_in[4];
    const float*         bout = (const float*)d_in[5];
    float*               out  = (float*)d_out;

    cudaFuncSetAttribute(flash_attn_kernel,
                         cudaFuncAttributeMaxDynamicSharedMemorySize, FA_SMEM);
    cudaFuncSetAttribute(qkv_gemm_kernel,
                         cudaFuncAttributeMaxDynamicSharedMemorySize, GEMM_SMEM);
    cudaFuncSetAttribute(out_gemm_kernel,
                         cudaFuncAttributeMaxDynamicSharedMemorySize, GEMM_SMEM);

    float *p_xc, *p_wqkv, *p_wout;
    cudaGetSymbolAddress((void**)&p_xc,   g_xc);
    cudaGetSymbolAddress((void**)&p_wqkv, g_wqkv);
    cudaGetSymbolAddress((void**)&p_wout, g_wout);

    rope_table_kernel<<<(L_SEQ * 32 + 255) / 256, 256>>>(pad);

    tf32_convert_kernel<<<592, 256>>>(x,    p_xc,   (M_ROWS * C_DIM) / 4);
    tf32_convert_kernel<<<592, 256>>>(Wqkv, p_wqkv, (C_DIM * N_QKV) / 4);
    tf32_convert_kernel<<<592, 256>>>(Wout, p_wout, (C_DIM * C_DIM) / 4);

    dim3 g1(N_QKV / 128, M_ROWS / 128);
    qkv_gemm_kernel<<<g1, 256, GEMM_SMEM>>>(bqkv);

    dim3 gr(L_SEQ / 64, BH_NUM);
    rope_transpose_kernel<<<gr, 256>>>();

    dim3 ga(L_SEQ / 128, BH_NUM);
    flash_attn_kernel<<<ga, 128, FA_SMEM>>>();

    dim3 g2(C_DIM / 128, M_ROWS / 128);
    out_gemm_kernel<<<g2, 256, GEMM_SMEM>>>(bout, out);
}